// round 1
// baseline (speedup 1.0000x reference)
#include <cuda_runtime.h>

// BlockLinear: y[b, o] = sum_{k<16} x[b, o*16+k] * w[o, k]
// B=8192, IN=32768, OUT=2048, BLOCK=16.
// Flattened: tid = b*2048 + o  ->  x elements [tid*16, tid*16+16) are contiguous.
// Pure HBM-streaming problem: 1 GiB x read + 64 MiB out write.

#define OUT_FEATURES 2048
#define TOTAL (8192 * 2048)

__global__ __launch_bounds__(256) void block_linear_kernel(
    const float4* __restrict__ x4,   // x viewed as float4: 4 per output
    const float4* __restrict__ w4,   // weight viewed as float4: 4 per row
    float* __restrict__ out)
{
    const int tid = blockIdx.x * blockDim.x + threadIdx.x;  // grid sized exactly
    const int o = tid & (OUT_FEATURES - 1);

    const float4* xp = x4 + ((long long)tid << 2);
    const float4* wp = w4 + (o << 2);

    // 8 independent 16B loads -> MLP=8, hides DRAM latency.
    float4 xv0 = xp[0];
    float4 xv1 = xp[1];
    float4 xv2 = xp[2];
    float4 xv3 = xp[3];
    float4 wv0 = wp[0];
    float4 wv1 = wp[1];
    float4 wv2 = wp[2];
    float4 wv3 = wp[3];

    float acc0 = xv0.x * wv0.x + xv0.y * wv0.y + xv0.z * wv0.z + xv0.w * wv0.w;
    float acc1 = xv1.x * wv1.x + xv1.y * wv1.y + xv1.z * wv1.z + xv1.w * wv1.w;
    float acc2 = xv2.x * wv2.x + xv2.y * wv2.y + xv2.z * wv2.z + xv2.w * wv2.w;
    float acc3 = xv3.x * wv3.x + xv3.y * wv3.y + xv3.z * wv3.z + xv3.w * wv3.w;

    out[tid] = (acc0 + acc1) + (acc2 + acc3);
}

extern "C" void kernel_launch(void* const* d_in, const int* in_sizes, int n_in,
                              void* d_out, int out_size)
{
    const float4* x4 = (const float4*)d_in[0];
    const float4* w4 = (const float4*)d_in[1];
    float* out = (float*)d_out;

    const int threads = 256;
    const int blocks = TOTAL / threads;  // 65536, exact
    block_linear_kernel<<<blocks, threads>>>(x4, w4, out);
}

// round 2
// speedup vs baseline: 1.0901x; 1.0901x over previous
#include <cuda_runtime.h>

// BlockLinear: y[b, o] = sum_{k<16} x[b, o*16+k] * w[o, k]
// B=8192, OUT=2048, BLOCK=16.
//
// R1 finding: L1tex wavefront-bound (97.8%) because per-lane weight loads
// (stride-64B across lanes) cost 16 wavefronts per LDG. Fix: pin weight in
// registers per thread (fixed o), iterate over G batch rows.

#define OUT_FEATURES 2048
#define B_ROWS 8192
#define G 16                       // batch rows per thread
#define BDIM 256
#define NTHREADS (B_ROWS / G * OUT_FEATURES)   // 1,048,576

__global__ __launch_bounds__(BDIM) void block_linear_kernel(
    const float4* __restrict__ x4,   // x as float4: index = (b*2048+o)*4 + j
    const float4* __restrict__ w4,   // weight as float4: index = o*4 + j
    float* __restrict__ out)
{
    const int t  = blockIdx.x * BDIM + threadIdx.x;   // [0, NTHREADS)
    const int o  = t & (OUT_FEATURES - 1);            // warp lanes: consecutive o
    const int b0 = t >> 11;                           // [0, B_ROWS/G)

    // Weight for this output row: loaded once, reused G times.
    const float4 w0 = w4[(o << 2) + 0];
    const float4 w1 = w4[(o << 2) + 1];
    const float4 w2 = w4[(o << 2) + 2];
    const float4 w3 = w4[(o << 2) + 3];

    #pragma unroll
    for (int g = 0; g < G; g++) {
        const int b = b0 + g * (B_ROWS / G);          // stride 512 rows
        const long long base = ((long long)b * OUT_FEATURES + o) << 2;

        // 4 independent coalesced 16B loads (512B/warp each -> 4 wavefronts)
        const float4 xv0 = x4[base + 0];
        const float4 xv1 = x4[base + 1];
        const float4 xv2 = x4[base + 2];
        const float4 xv3 = x4[base + 3];

        float acc0 = xv0.x * w0.x + xv0.y * w0.y + xv0.z * w0.z + xv0.w * w0.w;
        float acc1 = xv1.x * w1.x + xv1.y * w1.y + xv1.z * w1.z + xv1.w * w1.w;
        float acc2 = xv2.x * w2.x + xv2.y * w2.y + xv2.z * w2.z + xv2.w * w2.w;
        float acc3 = xv3.x * w3.x + xv3.y * w3.y + xv3.z * w3.z + xv3.w * w3.w;

        out[(long long)b * OUT_FEATURES + o] = (acc0 + acc1) + (acc2 + acc3);
    }
}

extern "C" void kernel_launch(void* const* d_in, const int* in_sizes, int n_in,
                              void* d_out, int out_size)
{
    const float4* x4 = (const float4*)d_in[0];
    const float4* w4 = (const float4*)d_in[1];
    float* out = (float*)d_out;

    block_linear_kernel<<<NTHREADS / BDIM, BDIM>>>(x4, w4, out);
}

// round 4
// speedup vs baseline: 1.3414x; 1.2306x over previous
#include <cuda_runtime.h>

// BlockLinear: y[b, o] = sum_{k<16} x[b, o*16+k] * w[o, k]
// B=8192, OUT=2048, BLOCK=16.
//
// R2 findings: L1tex still 90.6% (streaming x allocating in L1), occ reg-capped
// at 58.5%, per-thread b-stride 512 scattered TLB/L2 footprint.
// R3: streaming cache hints (ldcs/stcs), consecutive-b per thread, occ=6 blocks/SM.

#define OUT_FEATURES 2048
#define B_ROWS 8192
#define G 16                       // consecutive batch rows per thread
#define BDIM 256
#define NTHREADS (B_ROWS / G * OUT_FEATURES)   // 1,048,576

__global__ __launch_bounds__(BDIM, 6) void block_linear_kernel(
    const float4* __restrict__ x4,   // x as float4: index = (b*2048+o)*4 + j
    const float4* __restrict__ w4,   // weight as float4: index = o*4 + j
    float* __restrict__ out)
{
    const int t  = blockIdx.x * BDIM + threadIdx.x;   // [0, NTHREADS)
    const int o  = t & (OUT_FEATURES - 1);            // warp lanes: consecutive o
    const int b0 = (t >> 11) * G;                     // consecutive rows b0..b0+15

    // Weight for this output row: loaded once (L2-resident), reused G times.
    const float4 w0 = __ldg(&w4[(o << 2) + 0]);
    const float4 w1 = __ldg(&w4[(o << 2) + 1]);
    const float4 w2 = __ldg(&w4[(o << 2) + 2]);
    const float4 w3 = __ldg(&w4[(o << 2) + 3]);

    #pragma unroll
    for (int g = 0; g < G; g++) {
        const int b = b0 + g;
        const long long base = ((long long)b * OUT_FEATURES + o) << 2;

        // 4 independent coalesced 16B streaming loads (no L1 allocation)
        const float4 xv0 = __ldcs(&x4[base + 0]);
        const float4 xv1 = __ldcs(&x4[base + 1]);
        const float4 xv2 = __ldcs(&x4[base + 2]);
        const float4 xv3 = __ldcs(&x4[base + 3]);

        float acc0 = xv0.x * w0.x + xv0.y * w0.y + xv0.z * w0.z + xv0.w * w0.w;
        float acc1 = xv1.x * w1.x + xv1.y * w1.y + xv1.z * w1.z + xv1.w * w1.w;
        float acc2 = xv2.x * w2.x + xv2.y * w2.y + xv2.z * w2.z + xv2.w * w2.w;
        float acc3 = xv3.x * w3.x + xv3.y * w3.y + xv3.z * w3.z + xv3.w * w3.w;

        __stcs(&out[(long long)b * OUT_FEATURES + o], (acc0 + acc1) + (acc2 + acc3));
    }
}

extern "C" void kernel_launch(void* const* d_in, const int* in_sizes, int n_in,
                              void* d_out, int out_size)
{
    const float4* x4 = (const float4*)d_in[0];
    const float4* w4 = (const float4*)d_in[1];
    float* out = (float*)d_out;

    block_linear_kernel<<<NTHREADS / BDIM, BDIM>>>(x4, w4, out);
}

// round 5
// speedup vs baseline: 1.3542x; 1.0095x over previous
#include <cuda_runtime.h>

// BlockLinear: y[b, o] = sum_{k<16} x[b, o*16+k] * w[o, k]
// B=8192, OUT=2048, BLOCK=16.
//
// R4: 170us, DRAM=85%, time == DRAM service time. Remaining loss attributed to
// HBM read/write turnaround (stores sprinkled 1-per-16 load wavefronts).
// R5: accumulate all G outputs in registers, batch the 16 stores at thread end.
//     Relax occupancy cap to 4 blocks/SM for the extra accumulator registers.

#define OUT_FEATURES 2048
#define B_ROWS 8192
#define G 16                       // consecutive batch rows per thread
#define BDIM 256
#define NTHREADS (B_ROWS / G * OUT_FEATURES)   // 1,048,576

__global__ __launch_bounds__(BDIM, 4) void block_linear_kernel(
    const float4* __restrict__ x4,   // x as float4: index = (b*2048+o)*4 + j
    const float4* __restrict__ w4,   // weight as float4: index = o*4 + j
    float* __restrict__ out)
{
    const int t  = blockIdx.x * BDIM + threadIdx.x;   // [0, NTHREADS)
    const int o  = t & (OUT_FEATURES - 1);            // warp lanes: consecutive o
    const int b0 = (t >> 11) * G;                     // consecutive rows b0..b0+15

    // Weight for this output row: loaded once (L2-resident), reused G times.
    const float4 w0 = __ldg(&w4[(o << 2) + 0]);
    const float4 w1 = __ldg(&w4[(o << 2) + 1]);
    const float4 w2 = __ldg(&w4[(o << 2) + 2]);
    const float4 w3 = __ldg(&w4[(o << 2) + 3]);

    float acc[G];

    #pragma unroll
    for (int g = 0; g < G; g++) {
        const long long base = ((long long)(b0 + g) * OUT_FEATURES + o) << 2;

        // 4 independent coalesced 16B streaming loads (no L1 allocation)
        const float4 xv0 = __ldcs(&x4[base + 0]);
        const float4 xv1 = __ldcs(&x4[base + 1]);
        const float4 xv2 = __ldcs(&x4[base + 2]);
        const float4 xv3 = __ldcs(&x4[base + 3]);

        float a0 = xv0.x * w0.x + xv0.y * w0.y + xv0.z * w0.z + xv0.w * w0.w;
        float a1 = xv1.x * w1.x + xv1.y * w1.y + xv1.z * w1.z + xv1.w * w1.w;
        float a2 = xv2.x * w2.x + xv2.y * w2.y + xv2.z * w2.z + xv2.w * w2.w;
        float a3 = xv3.x * w3.x + xv3.y * w3.y + xv3.z * w3.z + xv3.w * w3.w;

        acc[g] = (a0 + a1) + (a2 + a3);
    }

    // Batched store phase: 16 coalesced store wavefronts back-to-back,
    // amortizing HBM read/write bus turnarounds.
    #pragma unroll
    for (int g = 0; g < G; g++) {
        __stcs(&out[(long long)(b0 + g) * OUT_FEATURES + o], acc[g]);
    }
}

extern "C" void kernel_launch(void* const* d_in, const int* in_sizes, int n_in,
                              void* d_out, int out_size)
{
    const float4* x4 = (const float4*)d_in[0];
    const float4* w4 = (const float4*)d_in[1];
    float* out = (float*)d_out;

    block_linear_kernel<<<NTHREADS / BDIM, BDIM>>>(x4, w4, out);
}

// round 6
// speedup vs baseline: 1.3799x; 1.0190x over previous
#include <cuda_runtime.h>

// BlockLinear: y[b, o] = sum_{k<16} x[b, o*16+k] * w[o, k]
// B=8192, OUT=2048, BLOCK=16.
//
// R5 finding: thread-owns-64B layout makes every warp LDG stride-64B across
// lanes: 16 wavefronts/load + duplicate 32B-sector fetches (L1=71%, L2=54%).
// R6: transposed warp tile — lane i, load j reads float4 #(j*32+i) of the
// warp's 2KB tile (perfectly coalesced), shfl_xor reduction over the 4 chunk
// lanes, permuted-but-contiguous 128B store.

#define OUT_FEATURES 2048
#define B_ROWS 8192
#define G 16                        // batch rows per warp tile
#define BDIM 256
#define WARPS_PER_BLK (BDIM / 32)
#define O_TILES (OUT_FEATURES / 32)          // 64
#define NBLOCKS ((B_ROWS / G) * O_TILES / WARPS_PER_BLK)   // 4096

__global__ __launch_bounds__(BDIM, 5) void block_linear_kernel(
    const float4* __restrict__ x4,   // x as float4
    const float4* __restrict__ w4,   // weight as float4: w4[o*4 + c]
    float* __restrict__ out)
{
    const int lane = threadIdx.x & 31;
    const int w    = blockIdx.x * WARPS_PER_BLK + (threadIdx.x >> 5);
    const int o_tile = (w & (O_TILES - 1)) << 5;   // 32 consecutive outputs
    const int b0     = (w >> 6) << 4;              // 16 consecutive batch rows

    const int c = lane & 3;    // chunk index within an output (4 float4 = 16 floats)
    const int r = lane >> 2;   // row-within-8 group

    // Weights for this warp's 32 outputs, distributed across lanes.
    // Lane (j): chunk c of output o_tile + j*8 + r. Coalesced, L2-resident.
    float4 wv0 = __ldg(&w4[(o_tile + 0 * 8 + r) * 4 + c]);
    float4 wv1 = __ldg(&w4[(o_tile + 1 * 8 + r) * 4 + c]);
    float4 wv2 = __ldg(&w4[(o_tile + 2 * 8 + r) * 4 + c]);
    float4 wv3 = __ldg(&w4[(o_tile + 3 * 8 + r) * 4 + c]);

    #pragma unroll
    for (int g = 0; g < G; g++) {
        const int b = b0 + g;
        const long long xbase = ((long long)b * OUT_FEATURES + o_tile) << 2; // float4 idx

        // Perfectly coalesced: 512B contiguous per warp-load, 4 loads = 2KB tile.
        const float4 xv0 = __ldcs(&x4[xbase + 0 * 32 + lane]);
        const float4 xv1 = __ldcs(&x4[xbase + 1 * 32 + lane]);
        const float4 xv2 = __ldcs(&x4[xbase + 2 * 32 + lane]);
        const float4 xv3 = __ldcs(&x4[xbase + 3 * 32 + lane]);

        // Partial dot: lane holds chunk c of output (j*8 + r_e) where for
        // element e=j*32+lane: chunk = lane&3 = c, out-in-tile = j*8 + lane/4.
        float p0 = xv0.x * wv0.x + xv0.y * wv0.y + xv0.z * wv0.z + xv0.w * wv0.w;
        float p1 = xv1.x * wv1.x + xv1.y * wv1.y + xv1.z * wv1.z + xv1.w * wv1.w;
        float p2 = xv2.x * wv2.x + xv2.y * wv2.y + xv2.z * wv2.z + xv2.w * wv2.w;
        float p3 = xv3.x * wv3.x + xv3.y * wv3.y + xv3.z * wv3.z + xv3.w * wv3.w;

        // Reduce the 4 chunk-lanes (lanes 4k..4k+3) of each output.
        p0 += __shfl_xor_sync(0xFFFFFFFFu, p0, 1);
        p1 += __shfl_xor_sync(0xFFFFFFFFu, p1, 1);
        p2 += __shfl_xor_sync(0xFFFFFFFFu, p2, 1);
        p3 += __shfl_xor_sync(0xFFFFFFFFu, p3, 1);
        p0 += __shfl_xor_sync(0xFFFFFFFFu, p0, 2);
        p1 += __shfl_xor_sync(0xFFFFFFFFu, p1, 2);
        p2 += __shfl_xor_sync(0xFFFFFFFFu, p2, 2);
        p3 += __shfl_xor_sync(0xFFFFFFFFu, p3, 2);

        // Lane i stores output (i%4)*8 + i/4 — bijective over the 32-output
        // tile, one contiguous 128B line per warp.
        const float v = (c == 0) ? p0 : (c == 1) ? p1 : (c == 2) ? p2 : p3;
        __stcs(&out[(long long)b * OUT_FEATURES + o_tile + c * 8 + r], v);
    }
}

extern "C" void kernel_launch(void* const* d_in, const int* in_sizes, int n_in,
                              void* d_out, int out_size)
{
    const float4* x4 = (const float4*)d_in[0];
    const float4* w4 = (const float4*)d_in[1];
    float* out = (float*)d_out;

    block_linear_kernel<<<NBLOCKS, BDIM>>>(x4, w4, out);
}